// round 11
// baseline (speedup 1.0000x reference)
#include <cuda_runtime.h>
#include <math.h>

// ---------------- problem constants ----------------
#define BATCH 64
#define MCH   12
#define NBM   768          // BATCH*MCH
#define DD    128
#define TT    256
#define LSEQ  2048
#define DI_   256
#define DSN   16
#define RKN   8

// ---------------- scratch (device globals; allocation-free) ----------------
__device__ float g_U   [(size_t)NBM*DD*TT];     // 96MB  xe / u (in-place residual)
__device__ float g_V   [(size_t)NBM*DD*TT];     // 96MB  gelu(dwconv(u))
__device__ float g_vbar[NBM*DD];
__device__ float g_a   [NBM*DD];
__device__ float g_xm  [(size_t)BATCH*TT*DD];   // (b,t,d)
__device__ float g_xz  [(size_t)BATCH*TT*512];
__device__ float g_xc  [(size_t)BATCH*TT*DI_];
__device__ float g_dbl [(size_t)BATCH*TT*40];
__device__ float g_dt  [(size_t)BATCH*TT*DI_];
__device__ float g_BC  [(size_t)BATCH*TT*32];   // Bm[0..15], Cm[16..31]
__device__ float g_y   [(size_t)BATCH*TT*DI_];
__device__ float g_mo  [(size_t)BATCH*TT*DD];

// ---------------- tf32 mma helpers ----------------
__device__ __forceinline__ unsigned f2tf(float x){
    unsigned r; asm("cvt.rna.tf32.f32 %0, %1;" : "=r"(r) : "f"(x)); return r;
}
__device__ __forceinline__ void mma8(float* c, unsigned a0,unsigned a1,unsigned a2,unsigned a3,
                                     unsigned b0,unsigned b1){
    asm volatile("mma.sync.aligned.m16n8k8.row.col.f32.tf32.tf32.f32 "
        "{%0,%1,%2,%3}, {%4,%5,%6,%7}, {%8,%9}, {%0,%1,%2,%3};"
        : "+f"(c[0]),"+f"(c[1]),"+f"(c[2]),"+f"(c[3])
        : "r"(a0),"r"(a1),"r"(a2),"r"(a3),"r"(b0),"r"(b1));
}

// ---------------- stage 1: strided embedding conv ----------------
__global__ void k_embed(const float* __restrict__ inp,
                        const float* __restrict__ ew,
                        const float* __restrict__ eb) {
    int bm = blockIdx.x;
    int b = bm / MCH, m = bm - b*MCH;
    __shared__ float xs[LSEQ];
    __shared__ float ws[DD*16];
    const float* src = inp + (size_t)b*LSEQ*MCH + m;
    for (int l = threadIdx.x; l < LSEQ; l += 256) xs[l] = src[(size_t)l*MCH];
    for (int i = threadIdx.x; i < DD*16; i += 256) ws[i] = ew[i];
    __syncthreads();
    float* dst = g_U + (size_t)bm*DD*TT;
    for (int o = threadIdx.x; o < DD*TT; o += 256) {
        int d = o >> 8, t = o & 255;
        int l0 = t*8 - 4;
        float acc = eb[d];
        #pragma unroll
        for (int p = 0; p < 16; p++) {
            int l = l0 + p;
            float x = (l >= 0 && l < LSEQ) ? xs[l] : 0.f;
            acc = fmaf(ws[d*16+p], x, acc);
        }
        dst[o] = acc;
    }
}

// ---------------- stage 2a: depthwise conv (K=5) + exact GELU + row mean ----------------
__global__ void k_dwconv(const float* __restrict__ dww,
                         const float* __restrict__ dwb, int li) {
    int row = blockIdx.x;              // bm*128 + d
    int d = row & 127;
    int tid = threadIdx.x;             // 256
    __shared__ float xs[TT+4];
    __shared__ float w[5];
    __shared__ float red[8];
    const float* u = g_U + (size_t)row*TT;
    xs[tid+2] = u[tid];
    if (tid < 2) { xs[tid] = 0.f; xs[tid+TT+2] = 0.f; }
    if (tid < 5) w[tid] = dww[li*DD*5 + d*5 + tid];
    __syncthreads();
    float acc = dwb[li*DD + d];
    #pragma unroll
    for (int j = 0; j < 5; j++) acc = fmaf(w[j], xs[tid+j], acc);
    float gl = 0.5f*acc*(1.f + erff(acc*0.70710678118654752f));   // exact gelu
    g_V[(size_t)row*TT + tid] = gl;
    float s = gl;
    #pragma unroll
    for (int o = 16; o > 0; o >>= 1) s += __shfl_down_sync(0xffffffffu, s, o);
    if ((tid & 31) == 0) red[tid >> 5] = s;
    __syncthreads();
    if (tid == 0) {
        float tot = 0.f;
        #pragma unroll
        for (int i = 0; i < 8; i++) tot += red[i];
        g_vbar[row] = tot * (1.f/256.f);
    }
}

// ---------------- stage 2b: SE gate from vbar ----------------
__global__ void k_se(const float* __restrict__ pww, const float* __restrict__ pwb,
                     const float* __restrict__ w1,  const float* __restrict__ b1,
                     const float* __restrict__ w2,  const float* __restrict__ b2, int li) {
    int bm = blockIdx.x, tid = threadIdx.x;   // 128 threads
    __shared__ float vb[DD], sv[DD], hs[32];
    vb[tid] = g_vbar[bm*DD + tid];
    __syncthreads();
    const float* pwr = pww + li*DD*DD + tid*DD;
    float acc = pwb[li*DD + tid];
    #pragma unroll 4
    for (int e = 0; e < DD; e++) acc = fmaf(pwr[e], vb[e], acc);
    sv[tid] = acc;
    __syncthreads();
    if (tid < 32) {
        const float* w1r = w1 + li*32*DD + tid*DD;
        float h = b1[li*32 + tid];
        #pragma unroll 4
        for (int d2 = 0; d2 < DD; d2++) h = fmaf(w1r[d2], sv[d2], h);
        hs[tid] = fmaxf(h, 0.f);
    }
    __syncthreads();
    const float* w2r = w2 + li*DD*32 + tid*32;
    float aa = b2[li*DD + tid];
    #pragma unroll
    for (int r = 0; r < 32; r++) aa = fmaf(w2r[r], hs[r], aa);
    g_a[bm*DD + tid] = 1.f/(1.f + __expf(-aa));
}

// ---------------- stage 2c: pointwise GEMM via tf32 mma, fused SE epilogue ----------------
// grid (4 n-tiles, 768 bm), block 256 (8 warps: 4m x 2n), tile 128x64x32
__global__ __launch_bounds__(256) void k_pw_mma(const float* __restrict__ pww,
                                                const float* __restrict__ pwb, int li) {
    __shared__ unsigned As[128*36];
    __shared__ unsigned Bs[64*36];
    int tid = threadIdx.x, wid = tid >> 5, lane = tid & 31;
    int wm = wid & 3, wn = wid >> 2;
    int n0 = blockIdx.x << 6;
    int bm = blockIdx.y;
    int g = lane >> 2, tg = lane & 3;
    const float* A  = pww + li*DD*DD;
    const float* Vb = g_V + (size_t)bm*DD*TT;
    float c[2][4][4] = {};
    for (int kb = 0; kb < 128; kb += 32) {
        #pragma unroll
        for (int p = 0; p < 4; p++) {
            int te = tid + p*256;
            int m = te >> 3, jj = (te & 7) << 2;
            float4 v = *(const float4*)&A[m*128 + kb + jj];
            unsigned* s = &As[m*36 + jj];
            s[0]=f2tf(v.x); s[1]=f2tf(v.y); s[2]=f2tf(v.z); s[3]=f2tf(v.w);
        }
        #pragma unroll
        for (int p = 0; p < 2; p++) {
            int te = tid + p*256;
            int e = te >> 4, nn = (te & 15) << 2;
            float4 v = *(const float4*)&Vb[(kb + e)*TT + n0 + nn];
            Bs[(nn+0)*36 + e] = f2tf(v.x);
            Bs[(nn+1)*36 + e] = f2tf(v.y);
            Bs[(nn+2)*36 + e] = f2tf(v.z);
            Bs[(nn+3)*36 + e] = f2tf(v.w);
        }
        __syncthreads();
        #pragma unroll
        for (int ks = 0; ks < 4; ks++) {
            int kk = ks*8;
            unsigned a[2][4], b[4][2];
            #pragma unroll
            for (int mi = 0; mi < 2; mi++) {
                int rb = wm*32 + mi*16 + g;
                a[mi][0] = As[rb*36 + kk + tg];
                a[mi][1] = As[(rb+8)*36 + kk + tg];
                a[mi][2] = As[rb*36 + kk + tg + 4];
                a[mi][3] = As[(rb+8)*36 + kk + tg + 4];
            }
            #pragma unroll
            for (int nj = 0; nj < 4; nj++) {
                int nb = wn*32 + nj*8 + g;
                b[nj][0] = Bs[nb*36 + kk + tg];
                b[nj][1] = Bs[nb*36 + kk + tg + 4];
            }
            #pragma unroll
            for (int mi = 0; mi < 2; mi++)
                #pragma unroll
                for (int nj = 0; nj < 4; nj++)
                    mma8(c[mi][nj], a[mi][0],a[mi][1],a[mi][2],a[mi][3], b[nj][0], b[nj][1]);
        }
        __syncthreads();
    }
    float* Ub = g_U + (size_t)bm*DD*TT;
    #pragma unroll
    for (int mi = 0; mi < 2; mi++) {
        int r0 = wm*32 + mi*16 + g;
        int r1 = r0 + 8;
        float bb0 = pwb[li*DD + r0], av0 = g_a[bm*DD + r0];
        float bb1 = pwb[li*DD + r1], av1 = g_a[bm*DD + r1];
        #pragma unroll
        for (int nj = 0; nj < 4; nj++) {
            int col = n0 + wn*32 + nj*8 + tg*2;
            float2* p0 = (float2*)&Ub[r0*TT + col];
            float2 u0 = *p0;
            u0.x += (c[mi][nj][0] + bb0)*av0;
            u0.y += (c[mi][nj][1] + bb0)*av0;
            *p0 = u0;
            float2* p1 = (float2*)&Ub[r1*TT + col];
            float2 u1 = *p1;
            u1.x += (c[mi][nj][2] + bb1)*av1;
            u1.y += (c[mi][nj][3] + bb1)*av1;
            *p1 = u1;
        }
    }
}

// ---------------- generic tf32 mma GEMM: C[M,N] = A[M,K] @ Bt[N,K]^T ----------------
// grid (M/128, ceil(N/64)), block 256; K multiple of 32; N ragged OK
__global__ __launch_bounds__(256) void k_gemm_mma(const float* __restrict__ A,
                                                  const float* __restrict__ Bt,
                                                  float* __restrict__ C,
                                                  int M, int N, int K) {
    __shared__ unsigned As[128*36];
    __shared__ unsigned Bs[64*36];
    int tid = threadIdx.x, wid = tid >> 5, lane = tid & 31;
    int wm = wid & 3, wn = wid >> 2;
    int m0 = blockIdx.x << 7, n0 = blockIdx.y << 6;
    int g = lane >> 2, tg = lane & 3;
    float c[2][4][4] = {};
    for (int kb = 0; kb < K; kb += 32) {
        #pragma unroll
        for (int p = 0; p < 4; p++) {
            int te = tid + p*256;
            int m = te >> 3, jj = (te & 7) << 2;
            float4 v = *(const float4*)&A[(size_t)(m0+m)*K + kb + jj];
            unsigned* s = &As[m*36 + jj];
            s[0]=f2tf(v.x); s[1]=f2tf(v.y); s[2]=f2tf(v.z); s[3]=f2tf(v.w);
        }
        #pragma unroll
        for (int p = 0; p < 2; p++) {
            int te = tid + p*256;
            int n = te >> 3, jj = (te & 7) << 2;
            float4 v = make_float4(0.f,0.f,0.f,0.f);
            if (n0 + n < N) v = *(const float4*)&Bt[(size_t)(n0+n)*K + kb + jj];
            unsigned* s = &Bs[n*36 + jj];
            s[0]=f2tf(v.x); s[1]=f2tf(v.y); s[2]=f2tf(v.z); s[3]=f2tf(v.w);
        }
        __syncthreads();
        #pragma unroll
        for (int ks = 0; ks < 4; ks++) {
            int kk = ks*8;
            unsigned a[2][4], b[4][2];
            #pragma unroll
            for (int mi = 0; mi < 2; mi++) {
                int rb = wm*32 + mi*16 + g;
                a[mi][0] = As[rb*36 + kk + tg];
                a[mi][1] = As[(rb+8)*36 + kk + tg];
                a[mi][2] = As[rb*36 + kk + tg + 4];
                a[mi][3] = As[(rb+8)*36 + kk + tg + 4];
            }
            #pragma unroll
            for (int nj = 0; nj < 4; nj++) {
                int nb = wn*32 + nj*8 + g;
                b[nj][0] = Bs[nb*36 + kk + tg];
                b[nj][1] = Bs[nb*36 + kk + tg + 4];
            }
            #pragma unroll
            for (int mi = 0; mi < 2; mi++)
                #pragma unroll
                for (int nj = 0; nj < 4; nj++)
                    mma8(c[mi][nj], a[mi][0],a[mi][1],a[mi][2],a[mi][3], b[nj][0], b[nj][1]);
        }
        __syncthreads();
    }
    #pragma unroll
    for (int mi = 0; mi < 2; mi++) {
        #pragma unroll
        for (int nj = 0; nj < 4; nj++) {
            int r0 = m0 + wm*32 + mi*16 + g;
            int col = n0 + wn*32 + nj*8 + tg*2;
            if (col < N) {
                C[(size_t)r0*N + col]       = c[mi][nj][0];
                C[(size_t)r0*N + col+1]     = c[mi][nj][1];
                C[(size_t)(r0+8)*N + col]   = c[mi][nj][2];
                C[(size_t)(r0+8)*N + col+1] = c[mi][nj][3];
            }
        }
    }
}

// ---------------- stage 3: pool over M sensors, layout -> (b,t,d) ----------------
__global__ void k_pool() {
    int b = blockIdx.x >> 7, d = blockIdx.x & 127;
    int t = threadIdx.x;
    float acc = 0.f;
    #pragma unroll
    for (int m = 0; m < MCH; m++)
        acc += g_U[((size_t)(b*MCH+m)*DD + d)*TT + t];
    g_xm[((size_t)b*TT + t)*DD + d] = acc * (1.f/12.f);
}

// ---------------- mamba: causal depthwise conv (DC=4) + silu ----------------
__global__ void k_conv_silu(const float* __restrict__ cw, const float* __restrict__ cb, int li) {
    int idx = blockIdx.x*256 + threadIdx.x;         // (b,t,c)
    int c = idx & 255, t = (idx >> 8) & 255, b = idx >> 16;
    const float* xzb = g_xz + (size_t)b*TT*512 + c;
    float acc = cb[li*DI_ + c];
    const float* wr = cw + li*DI_*4 + c*4;
    #pragma unroll
    for (int j = 0; j < 4; j++) {
        int tt = t - 3 + j;
        if (tt >= 0) acc = fmaf(wr[j], xzb[(size_t)tt*512], acc);
    }
    float sg = 1.f/(1.f + __expf(-acc));
    g_xc[(size_t)idx] = acc * sg;
}

// ---------------- mamba: dt = softplus(dt_w@dtr + dt_b); split B,C ----------------
__global__ void k_dtsplit(const float* __restrict__ dtw, const float* __restrict__ dtb, int li) {
    int row = blockIdx.x;           // b*256+t
    int c = threadIdx.x;            // 256
    __shared__ float sd[40];
    if (c < 40) sd[c] = g_dbl[(size_t)row*40 + c];
    __syncthreads();
    float v = dtb[li*DI_ + c];
    const float* wr = dtw + li*DI_*RKN + c*RKN;
    #pragma unroll
    for (int r = 0; r < RKN; r++) v = fmaf(wr[r], sd[r], v);
    float sp = (v > 20.f) ? v : log1pf(__expf(v));
    g_dt[(size_t)row*DI_ + c] = sp;
    if (c < 32) g_BC[(size_t)row*32 + c] = sd[8 + c];
}

// ---------------- mamba: sequential selective scan ----------------
__global__ void k_scan(const float* __restrict__ Alog, const float* __restrict__ Dpar, int li) {
    int b = blockIdx.x, c = threadIdx.x;   // 64 blocks x 256 threads
    float E[DSN];
    bool ip = true;
    #pragma unroll
    for (int s = 0; s < DSN; s++) {
        float e = __expf(Alog[li*DI_*DSN + c*DSN + s]);
        E[s] = e;
        ip = ip && (fabsf(e - (float)(s+1)) < 2e-3f);
    }
    float h[DSN];
    #pragma unroll
    for (int s = 0; s < DSN; s++) h[s] = 0.f;
    float dp = Dpar[li*DI_ + c];
    size_t base0 = (size_t)b*TT;
    float dtv = g_dt[base0*DI_ + c];
    float xcv = g_xc[base0*DI_ + c];
    float zv  = g_xz[base0*512 + 256 + c];
    for (int t = 0; t < TT; t++) {
        size_t base = base0 + t;
        float dtc = dtv, xcc = xcv, zc = zv;
        if (t < TT-1) {
            dtv = g_dt[(base+1)*DI_ + c];
            xcv = g_xc[(base+1)*DI_ + c];
            zv  = g_xz[(base+1)*512 + 256 + c];
        }
        const float* bc = g_BC + base*32;
        float acc = 0.f;
        float dx = dtc * xcc;
        if (ip) {
            float q = __expf(-dtc);
            float p = 1.f;
            #pragma unroll
            for (int s = 0; s < DSN; s++) {
                p *= q;
                h[s] = fmaf(p, h[s], dx*bc[s]);
                acc  = fmaf(h[s], bc[16+s], acc);
            }
        } else {
            #pragma unroll
            for (int s = 0; s < DSN; s++) {
                float dA = __expf(-dtc*E[s]);
                h[s] = fmaf(dA, h[s], dx*bc[s]);
                acc  = fmaf(h[s], bc[16+s], acc);
            }
        }
        float yv = acc + dp*xcc;
        float sg = 1.f/(1.f + __expf(-zc));
        yv *= zc*sg;
        g_y[base*DI_ + c] = yv;
    }
}

// ---------------- residual + layernorm (rows of 128) ----------------
__global__ void k_ln(const float* __restrict__ lng, const float* __restrict__ lnb, int li) {
    int wid = threadIdx.x >> 5, lane = threadIdx.x & 31;
    int row = blockIdx.x*8 + wid;
    const float4* xm4 = (const float4*)(g_xm + (size_t)row*DD);
    const float4* mo4 = (const float4*)(g_mo + (size_t)row*DD);
    float4 a = xm4[lane], m = mo4[lane];
    float v0 = a.x+m.x, v1 = a.y+m.y, v2 = a.z+m.z, v3 = a.w+m.w;
    float s = v0+v1+v2+v3;
    #pragma unroll
    for (int o = 16; o > 0; o >>= 1) s += __shfl_xor_sync(0xffffffffu, s, o);
    float mu = s * (1.f/128.f);
    float d0 = v0-mu, d1 = v1-mu, d2 = v2-mu, d3 = v3-mu;
    float vs = d0*d0 + d1*d1 + d2*d2 + d3*d3;
    #pragma unroll
    for (int o = 16; o > 0; o >>= 1) vs += __shfl_xor_sync(0xffffffffu, vs, o);
    float rs = rsqrtf(vs*(1.f/128.f) + 1e-5f);
    int dd = lane*4;
    float4 gg = *(const float4*)(lng + li*DD + dd);
    float4 bb = *(const float4*)(lnb + li*DD + dd);
    float4 o4;
    o4.x = d0*rs*gg.x + bb.x;
    o4.y = d1*rs*gg.y + bb.y;
    o4.z = d2*rs*gg.z + bb.z;
    o4.w = d3*rs*gg.w + bb.w;
    ((float4*)(g_xm + (size_t)row*DD))[lane] = o4;
}

// ---------------- final: xflat transpose (b,t,d)->(b,d,t) ----------------
__global__ void k_transpose(float* __restrict__ out) {
    __shared__ float tile[32][33];
    int b = blockIdx.x, t0 = blockIdx.y << 5, d0 = blockIdx.z << 5;
    int tx = threadIdx.x, ty = threadIdx.y;  // 32x8
    const float* src = g_xm + (size_t)b*DD*TT;
    #pragma unroll
    for (int r = ty; r < 32; r += 8)
        tile[r][tx] = src[(size_t)(t0+r)*DD + d0 + tx];
    __syncthreads();
    float* dst = out + (size_t)b*DD*TT;
    #pragma unroll
    for (int r = ty; r < 32; r += 8)
        dst[(size_t)(d0+r)*TT + t0 + tx] = tile[tx][r];
}

// ---------------- final: pred = xflat @ fc_w^T + fc_b ----------------
__global__ void k_pred(const float* __restrict__ xflat, const float* __restrict__ fcw,
                       const float* __restrict__ fcb, float* __restrict__ pred) {
    int b = blockIdx.x, tid = threadIdx.x;
    float acc[18];
    #pragma unroll
    for (int c = 0; c < 18; c++) acc[c] = 0.f;
    const float* xr = xflat + (size_t)b*32768;
    for (int k = tid; k < 32768; k += 256) {
        float x = xr[k];
        #pragma unroll
        for (int c = 0; c < 18; c++)
            acc[c] = fmaf(x, fcw[(size_t)c*32768 + k], acc[c]);
    }
    __shared__ float red[8*18];
    int lane = tid & 31, wid = tid >> 5;
    #pragma unroll
    for (int c = 0; c < 18; c++) {
        float s = acc[c];
        #pragma unroll
        for (int o = 16; o > 0; o >>= 1) s += __shfl_xor_sync(0xffffffffu, s, o);
        if (lane == 0) red[wid*18 + c] = s;
    }
    __syncthreads();
    if (tid < 18) {
        float s = fcb[tid];
        #pragma unroll
        for (int w = 0; w < 8; w++) s += red[w*18 + tid];
        pred[b*18 + tid] = s;
    }
}

// ---------------- launch ----------------
extern "C" void kernel_launch(void* const* d_in, const int* in_sizes, int n_in,
                              void* d_out, int out_size) {
    const float* inp   = (const float*)d_in[0];
    const float* emb_w = (const float*)d_in[1];
    const float* emb_b = (const float*)d_in[2];
    const float* dww   = (const float*)d_in[3];
    const float* dwb   = (const float*)d_in[4];
    const float* pww   = (const float*)d_in[5];
    const float* pwb   = (const float*)d_in[6];
    const float* sw1   = (const float*)d_in[7];
    const float* sb1   = (const float*)d_in[8];
    const float* sw2   = (const float*)d_in[9];
    const float* sb2   = (const float*)d_in[10];
    const float* minw  = (const float*)d_in[11];
    const float* mcw   = (const float*)d_in[12];
    const float* mcb   = (const float*)d_in[13];
    const float* mxp   = (const float*)d_in[14];
    const float* mdtw  = (const float*)d_in[15];
    const float* mdtb  = (const float*)d_in[16];
    const float* mAlog = (const float*)d_in[17];
    const float* mD    = (const float*)d_in[18];
    const float* mow   = (const float*)d_in[19];
    const float* lng   = (const float*)d_in[20];
    const float* lnb   = (const float*)d_in[21];
    const float* fcw   = (const float*)d_in[22];
    const float* fcb   = (const float*)d_in[23];
    float* out = (float*)d_out;

    float *pxm, *pxz, *pxc, *pdbl, *py, *pmo;
    cudaGetSymbolAddress((void**)&pxm,  g_xm);
    cudaGetSymbolAddress((void**)&pxz,  g_xz);
    cudaGetSymbolAddress((void**)&pxc,  g_xc);
    cudaGetSymbolAddress((void**)&pdbl, g_dbl);
    cudaGetSymbolAddress((void**)&py,   g_y);
    cudaGetSymbolAddress((void**)&pmo,  g_mo);

    // embedding
    k_embed<<<NBM, 256>>>(inp, emb_w, emb_b);

    // 3 conv blocks
    for (int li = 0; li < 3; li++) {
        k_dwconv<<<NBM*DD, 256>>>(dww, dwb, li);
        k_se<<<NBM, 128>>>(pww, pwb, sw1, sb1, sw2, sb2, li);
        dim3 gpw(4, NBM);
        k_pw_mma<<<gpw, 256>>>(pww, pwb, li);
    }

    // pool -> (b,t,d)
    k_pool<<<BATCH*DD, 256>>>();

    // 2 mamba layers
    for (int li = 0; li < 2; li++) {
        dim3 gxz(16384/128, 512/64);
        k_gemm_mma<<<gxz, 256>>>(pxm, minw + (size_t)li*512*DD, pxz, 16384, 512, 128);
        k_conv_silu<<<(BATCH*TT*DI_)/256, 256>>>(mcw, mcb, li);
        dim3 gdb(16384/128, 1);
        k_gemm_mma<<<gdb, 256>>>(pxc, mxp + (size_t)li*40*DI_, pdbl, 16384, 40, 256);
        k_dtsplit<<<BATCH*TT, 256>>>(mdtw, mdtb, li);
        k_scan<<<BATCH, 256>>>(mAlog, mD, li);
        dim3 gout(16384/128, 2);
        k_gemm_mma<<<gout, 256>>>(py, mow + (size_t)li*DD*DI_, pmo, 16384, 128, 256);
        k_ln<<<16384/8, 256>>>(lng, lnb, li);
    }

    // outputs: xflat (64*32768) then pred (64*18)
    dim3 gt(BATCH, TT/32, DD/32);
    k_transpose<<<gt, dim3(32, 8)>>>(out);
    k_pred<<<BATCH, 256>>>(out, fcw, fcb, out + (size_t)BATCH*DD*TT);
}

// round 13
// speedup vs baseline: 1.0066x; 1.0066x over previous
#include <cuda_runtime.h>
#include <math.h>

// ---------------- problem constants ----------------
#define BATCH 64
#define MCH   12
#define NBM   768          // BATCH*MCH
#define DD    128
#define TT    256
#define LSEQ  2048
#define DI_   256
#define DSN   16
#define RKN   8

// ---------------- scratch (device globals; allocation-free) ----------------
__device__ float g_U   [(size_t)NBM*DD*TT];     // 96MB  xe / u (in-place residual)
__device__ float g_V   [(size_t)NBM*DD*TT];     // 96MB  gelu(dwconv(u))
__device__ float g_vbar[NBM*DD];
__device__ float g_a   [NBM*DD];
__device__ float g_xm  [(size_t)BATCH*TT*DD];   // (b,t,d)
__device__ float g_xz  [(size_t)BATCH*TT*512];
__device__ float g_xc  [(size_t)BATCH*TT*DI_];
__device__ float g_dbl [(size_t)BATCH*TT*40];
__device__ float g_dt  [(size_t)BATCH*TT*DI_];
__device__ float g_BC  [(size_t)BATCH*TT*32];   // Bm[0..15], Cm[16..31]
__device__ float g_y   [(size_t)BATCH*TT*DI_];
__device__ float g_mo  [(size_t)BATCH*TT*DD];

// ---------------- tf32 mma helpers ----------------
__device__ __forceinline__ unsigned f2tf(float x){
    unsigned r; asm("cvt.rna.tf32.f32 %0, %1;" : "=r"(r) : "f"(x)); return r;
}
__device__ __forceinline__ void mma8(float* c, unsigned a0,unsigned a1,unsigned a2,unsigned a3,
                                     unsigned b0,unsigned b1){
    asm volatile("mma.sync.aligned.m16n8k8.row.col.f32.tf32.tf32.f32 "
        "{%0,%1,%2,%3}, {%4,%5,%6,%7}, {%8,%9}, {%0,%1,%2,%3};"
        : "+f"(c[0]),"+f"(c[1]),"+f"(c[2]),"+f"(c[3])
        : "r"(a0),"r"(a1),"r"(a2),"r"(a3),"r"(b0),"r"(b1));
}

// ---------------- stage 1: strided embedding conv ----------------
__global__ void k_embed(const float* __restrict__ inp,
                        const float* __restrict__ ew,
                        const float* __restrict__ eb) {
    int bm = blockIdx.x;
    int b = bm / MCH, m = bm - b*MCH;
    __shared__ float xs[LSEQ];
    __shared__ float ws[DD*16];
    const float* src = inp + (size_t)b*LSEQ*MCH + m;
    for (int l = threadIdx.x; l < LSEQ; l += 256) xs[l] = src[(size_t)l*MCH];
    for (int i = threadIdx.x; i < DD*16; i += 256) ws[i] = ew[i];
    __syncthreads();
    float* dst = g_U + (size_t)bm*DD*TT;
    for (int o = threadIdx.x; o < DD*TT; o += 256) {
        int d = o >> 8, t = o & 255;
        int l0 = t*8 - 4;
        float acc = eb[d];
        #pragma unroll
        for (int p = 0; p < 16; p++) {
            int l = l0 + p;
            float x = (l >= 0 && l < LSEQ) ? xs[l] : 0.f;
            acc = fmaf(ws[d*16+p], x, acc);
        }
        dst[o] = acc;
    }
}

// ---------------- stage 2a: depthwise conv (K=5) + exact GELU + row mean ----------------
__global__ void k_dwconv(const float* __restrict__ dww,
                         const float* __restrict__ dwb, int li) {
    int row = blockIdx.x;              // bm*128 + d
    int d = row & 127;
    int tid = threadIdx.x;             // 256
    __shared__ float xs[TT+4];
    __shared__ float w[5];
    __shared__ float red[8];
    const float* u = g_U + (size_t)row*TT;
    xs[tid+2] = u[tid];
    if (tid < 2) { xs[tid] = 0.f; xs[tid+TT+2] = 0.f; }
    if (tid < 5) w[tid] = dww[li*DD*5 + d*5 + tid];
    __syncthreads();
    float acc = dwb[li*DD + d];
    #pragma unroll
    for (int j = 0; j < 5; j++) acc = fmaf(w[j], xs[tid+j], acc);
    float gl = 0.5f*acc*(1.f + erff(acc*0.70710678118654752f));   // exact gelu
    g_V[(size_t)row*TT + tid] = gl;
    float s = gl;
    #pragma unroll
    for (int o = 16; o > 0; o >>= 1) s += __shfl_down_sync(0xffffffffu, s, o);
    if ((tid & 31) == 0) red[tid >> 5] = s;
    __syncthreads();
    if (tid == 0) {
        float tot = 0.f;
        #pragma unroll
        for (int i = 0; i < 8; i++) tot += red[i];
        g_vbar[row] = tot * (1.f/256.f);
    }
}

// ---------------- stage 2b: SE gate from vbar ----------------
__global__ void k_se(const float* __restrict__ pww, const float* __restrict__ pwb,
                     const float* __restrict__ w1,  const float* __restrict__ b1,
                     const float* __restrict__ w2,  const float* __restrict__ b2, int li) {
    int bm = blockIdx.x, tid = threadIdx.x;   // 128 threads
    __shared__ float vb[DD], sv[DD], hs[32];
    vb[tid] = g_vbar[bm*DD + tid];
    __syncthreads();
    const float* pwr = pww + li*DD*DD + tid*DD;
    float acc = pwb[li*DD + tid];
    #pragma unroll 4
    for (int e = 0; e < DD; e++) acc = fmaf(pwr[e], vb[e], acc);
    sv[tid] = acc;
    __syncthreads();
    if (tid < 32) {
        const float* w1r = w1 + li*32*DD + tid*DD;
        float h = b1[li*32 + tid];
        #pragma unroll 4
        for (int d2 = 0; d2 < DD; d2++) h = fmaf(w1r[d2], sv[d2], h);
        hs[tid] = fmaxf(h, 0.f);
    }
    __syncthreads();
    const float* w2r = w2 + li*DD*32 + tid*32;
    float aa = b2[li*DD + tid];
    #pragma unroll
    for (int r = 0; r < 32; r++) aa = fmaf(w2r[r], hs[r], aa);
    g_a[bm*DD + tid] = 1.f/(1.f + __expf(-aa));
}

// ---------------- stage 2c: pointwise GEMM via tf32 mma, fused SE epilogue ----------------
// grid (4 n-tiles, 768 bm), block 256 (8 warps: 4m x 2n), tile 128x64x32
__global__ __launch_bounds__(256) void k_pw_mma(const float* __restrict__ pww,
                                                const float* __restrict__ pwb, int li) {
    __shared__ unsigned As[128*36];
    __shared__ unsigned Bs[64*36];
    int tid = threadIdx.x, wid = tid >> 5, lane = tid & 31;
    int wm = wid & 3, wn = wid >> 2;
    int n0 = blockIdx.x << 6;
    int bm = blockIdx.y;
    int g = lane >> 2, tg = lane & 3;
    const float* A  = pww + li*DD*DD;
    const float* Vb = g_V + (size_t)bm*DD*TT;
    float c[2][4][4] = {};
    for (int kb = 0; kb < 128; kb += 32) {
        #pragma unroll
        for (int p = 0; p < 4; p++) {
            int te = tid + p*256;
            int m = te >> 3, jj = (te & 7) << 2;
            float4 v = *(const float4*)&A[m*128 + kb + jj];
            unsigned* s = &As[m*36 + jj];
            s[0]=f2tf(v.x); s[1]=f2tf(v.y); s[2]=f2tf(v.z); s[3]=f2tf(v.w);
        }
        #pragma unroll
        for (int p = 0; p < 2; p++) {
            int te = tid + p*256;
            int e = te >> 4, nn = (te & 15) << 2;
            float4 v = *(const float4*)&Vb[(kb + e)*TT + n0 + nn];
            Bs[(nn+0)*36 + e] = f2tf(v.x);
            Bs[(nn+1)*36 + e] = f2tf(v.y);
            Bs[(nn+2)*36 + e] = f2tf(v.z);
            Bs[(nn+3)*36 + e] = f2tf(v.w);
        }
        __syncthreads();
        #pragma unroll
        for (int ks = 0; ks < 4; ks++) {
            int kk = ks*8;
            unsigned a[2][4], b[4][2];
            #pragma unroll
            for (int mi = 0; mi < 2; mi++) {
                int rb = wm*32 + mi*16 + g;
                a[mi][0] = As[rb*36 + kk + tg];
                a[mi][1] = As[(rb+8)*36 + kk + tg];
                a[mi][2] = As[rb*36 + kk + tg + 4];
                a[mi][3] = As[(rb+8)*36 + kk + tg + 4];
            }
            #pragma unroll
            for (int nj = 0; nj < 4; nj++) {
                int nb = wn*32 + nj*8 + g;
                b[nj][0] = Bs[nb*36 + kk + tg];
                b[nj][1] = Bs[nb*36 + kk + tg + 4];
            }
            #pragma unroll
            for (int mi = 0; mi < 2; mi++)
                #pragma unroll
                for (int nj = 0; nj < 4; nj++)
                    mma8(c[mi][nj], a[mi][0],a[mi][1],a[mi][2],a[mi][3], b[nj][0], b[nj][1]);
        }
        __syncthreads();
    }
    float* Ub = g_U + (size_t)bm*DD*TT;
    #pragma unroll
    for (int mi = 0; mi < 2; mi++) {
        int r0 = wm*32 + mi*16 + g;
        int r1 = r0 + 8;
        float bb0 = pwb[li*DD + r0], av0 = g_a[bm*DD + r0];
        float bb1 = pwb[li*DD + r1], av1 = g_a[bm*DD + r1];
        #pragma unroll
        for (int nj = 0; nj < 4; nj++) {
            int col = n0 + wn*32 + nj*8 + tg*2;
            float2* p0 = (float2*)&Ub[r0*TT + col];
            float2 u0 = *p0;
            u0.x += (c[mi][nj][0] + bb0)*av0;
            u0.y += (c[mi][nj][1] + bb0)*av0;
            *p0 = u0;
            float2* p1 = (float2*)&Ub[r1*TT + col];
            float2 u1 = *p1;
            u1.x += (c[mi][nj][2] + bb1)*av1;
            u1.y += (c[mi][nj][3] + bb1)*av1;
            *p1 = u1;
        }
    }
}

// ---------------- generic tf32 mma GEMM: C[M,N] = A[M,K] @ Bt[N,K]^T ----------------
// grid (M/128, ceil(N/64)), block 256; K multiple of 32; N ragged OK
__global__ __launch_bounds__(256) void k_gemm_mma(const float* __restrict__ A,
                                                  const float* __restrict__ Bt,
                                                  float* __restrict__ C,
                                                  int M, int N, int K) {
    __shared__ unsigned As[128*36];
    __shared__ unsigned Bs[64*36];
    int tid = threadIdx.x, wid = tid >> 5, lane = tid & 31;
    int wm = wid & 3, wn = wid >> 2;
    int m0 = blockIdx.x << 7, n0 = blockIdx.y << 6;
    int g = lane >> 2, tg = lane & 3;
    float c[2][4][4] = {};
    for (int kb = 0; kb < K; kb += 32) {
        #pragma unroll
        for (int p = 0; p < 4; p++) {
            int te = tid + p*256;
            int m = te >> 3, jj = (te & 7) << 2;
            float4 v = *(const float4*)&A[(size_t)(m0+m)*K + kb + jj];
            unsigned* s = &As[m*36 + jj];
            s[0]=f2tf(v.x); s[1]=f2tf(v.y); s[2]=f2tf(v.z); s[3]=f2tf(v.w);
        }
        #pragma unroll
        for (int p = 0; p < 2; p++) {
            int te = tid + p*256;
            int n = te >> 3, jj = (te & 7) << 2;
            float4 v = make_float4(0.f,0.f,0.f,0.f);
            if (n0 + n < N) v = *(const float4*)&Bt[(size_t)(n0+n)*K + kb + jj];
            unsigned* s = &Bs[n*36 + jj];
            s[0]=f2tf(v.x); s[1]=f2tf(v.y); s[2]=f2tf(v.z); s[3]=f2tf(v.w);
        }
        __syncthreads();
        #pragma unroll
        for (int ks = 0; ks < 4; ks++) {
            int kk = ks*8;
            unsigned a[2][4], b[4][2];
            #pragma unroll
            for (int mi = 0; mi < 2; mi++) {
                int rb = wm*32 + mi*16 + g;
                a[mi][0] = As[rb*36 + kk + tg];
                a[mi][1] = As[(rb+8)*36 + kk + tg];
                a[mi][2] = As[rb*36 + kk + tg + 4];
                a[mi][3] = As[(rb+8)*36 + kk + tg + 4];
            }
            #pragma unroll
            for (int nj = 0; nj < 4; nj++) {
                int nb = wn*32 + nj*8 + g;
                b[nj][0] = Bs[nb*36 + kk + tg];
                b[nj][1] = Bs[nb*36 + kk + tg + 4];
            }
            #pragma unroll
            for (int mi = 0; mi < 2; mi++)
                #pragma unroll
                for (int nj = 0; nj < 4; nj++)
                    mma8(c[mi][nj], a[mi][0],a[mi][1],a[mi][2],a[mi][3], b[nj][0], b[nj][1]);
        }
        __syncthreads();
    }
    #pragma unroll
    for (int mi = 0; mi < 2; mi++) {
        #pragma unroll
        for (int nj = 0; nj < 4; nj++) {
            int r0 = m0 + wm*32 + mi*16 + g;
            int col = n0 + wn*32 + nj*8 + tg*2;
            if (col < N) {
                C[(size_t)r0*N + col]       = c[mi][nj][0];
                C[(size_t)r0*N + col+1]     = c[mi][nj][1];
                C[(size_t)(r0+8)*N + col]   = c[mi][nj][2];
                C[(size_t)(r0+8)*N + col+1] = c[mi][nj][3];
            }
        }
    }
}

// ---------------- stage 3: pool over M sensors, layout -> (b,t,d) ----------------
__global__ void k_pool() {
    int b = blockIdx.x >> 7, d = blockIdx.x & 127;
    int t = threadIdx.x;
    float acc = 0.f;
    #pragma unroll
    for (int m = 0; m < MCH; m++)
        acc += g_U[((size_t)(b*MCH+m)*DD + d)*TT + t];
    g_xm[((size_t)b*TT + t)*DD + d] = acc * (1.f/12.f);
}

// ---------------- mamba: causal depthwise conv (DC=4) + silu ----------------
__global__ void k_conv_silu(const float* __restrict__ cw, const float* __restrict__ cb, int li) {
    int idx = blockIdx.x*256 + threadIdx.x;         // (b,t,c)
    int c = idx & 255, t = (idx >> 8) & 255, b = idx >> 16;
    const float* xzb = g_xz + (size_t)b*TT*512 + c;
    float acc = cb[li*DI_ + c];
    const float* wr = cw + li*DI_*4 + c*4;
    #pragma unroll
    for (int j = 0; j < 4; j++) {
        int tt = t - 3 + j;
        if (tt >= 0) acc = fmaf(wr[j], xzb[(size_t)tt*512], acc);
    }
    float sg = 1.f/(1.f + __expf(-acc));
    g_xc[(size_t)idx] = acc * sg;
}

// ---------------- mamba: dt = softplus(dt_w@dtr + dt_b); split B,C ----------------
__global__ void k_dtsplit(const float* __restrict__ dtw, const float* __restrict__ dtb, int li) {
    int row = blockIdx.x;           // b*256+t
    int c = threadIdx.x;            // 256
    __shared__ float sd[40];
    if (c < 40) sd[c] = g_dbl[(size_t)row*40 + c];
    __syncthreads();
    float v = dtb[li*DI_ + c];
    const float* wr = dtw + li*DI_*RKN + c*RKN;
    #pragma unroll
    for (int r = 0; r < RKN; r++) v = fmaf(wr[r], sd[r], v);
    float sp = (v > 20.f) ? v : log1pf(__expf(v));
    g_dt[(size_t)row*DI_ + c] = sp;
    if (c < 32) g_BC[(size_t)row*32 + c] = sd[8 + c];
}

// ---------------- mamba: sequential selective scan ----------------
__global__ void k_scan(const float* __restrict__ Alog, const float* __restrict__ Dpar, int li) {
    int b = blockIdx.x, c = threadIdx.x;   // 64 blocks x 256 threads
    float E[DSN];
    bool ip = true;
    #pragma unroll
    for (int s = 0; s < DSN; s++) {
        float e = __expf(Alog[li*DI_*DSN + c*DSN + s]);
        E[s] = e;
        ip = ip && (fabsf(e - (float)(s+1)) < 2e-3f);
    }
    float h[DSN];
    #pragma unroll
    for (int s = 0; s < DSN; s++) h[s] = 0.f;
    float dp = Dpar[li*DI_ + c];
    size_t base0 = (size_t)b*TT;
    float dtv = g_dt[base0*DI_ + c];
    float xcv = g_xc[base0*DI_ + c];
    float zv  = g_xz[base0*512 + 256 + c];
    for (int t = 0; t < TT; t++) {
        size_t base = base0 + t;
        float dtc = dtv, xcc = xcv, zc = zv;
        if (t < TT-1) {
            dtv = g_dt[(base+1)*DI_ + c];
            xcv = g_xc[(base+1)*DI_ + c];
            zv  = g_xz[(base+1)*512 + 256 + c];
        }
        const float* bc = g_BC + base*32;
        float acc = 0.f;
        float dx = dtc * xcc;
        if (ip) {
            float q = __expf(-dtc);
            float p = 1.f;
            #pragma unroll
            for (int s = 0; s < DSN; s++) {
                p *= q;
                h[s] = fmaf(p, h[s], dx*bc[s]);
                acc  = fmaf(h[s], bc[16+s], acc);
            }
        } else {
            #pragma unroll
            for (int s = 0; s < DSN; s++) {
                float dA = __expf(-dtc*E[s]);
                h[s] = fmaf(dA, h[s], dx*bc[s]);
                acc  = fmaf(h[s], bc[16+s], acc);
            }
        }
        float yv = acc + dp*xcc;
        float sg = 1.f/(1.f + __expf(-zc));
        yv *= zc*sg;
        g_y[base*DI_ + c] = yv;
    }
}

// ---------------- residual + layernorm (rows of 128) ----------------
__global__ void k_ln(const float* __restrict__ lng, const float* __restrict__ lnb, int li) {
    int wid = threadIdx.x >> 5, lane = threadIdx.x & 31;
    int row = blockIdx.x*8 + wid;
    const float4* xm4 = (const float4*)(g_xm + (size_t)row*DD);
    const float4* mo4 = (const float4*)(g_mo + (size_t)row*DD);
    float4 a = xm4[lane], m = mo4[lane];
    float v0 = a.x+m.x, v1 = a.y+m.y, v2 = a.z+m.z, v3 = a.w+m.w;
    float s = v0+v1+v2+v3;
    #pragma unroll
    for (int o = 16; o > 0; o >>= 1) s += __shfl_xor_sync(0xffffffffu, s, o);
    float mu = s * (1.f/128.f);
    float d0 = v0-mu, d1 = v1-mu, d2 = v2-mu, d3 = v3-mu;
    float vs = d0*d0 + d1*d1 + d2*d2 + d3*d3;
    #pragma unroll
    for (int o = 16; o > 0; o >>= 1) vs += __shfl_xor_sync(0xffffffffu, vs, o);
    float rs = rsqrtf(vs*(1.f/128.f) + 1e-5f);
    int dd = lane*4;
    float4 gg = *(const float4*)(lng + li*DD + dd);
    float4 bb = *(const float4*)(lnb + li*DD + dd);
    float4 o4;
    o4.x = d0*rs*gg.x + bb.x;
    o4.y = d1*rs*gg.y + bb.y;
    o4.z = d2*rs*gg.z + bb.z;
    o4.w = d3*rs*gg.w + bb.w;
    ((float4*)(g_xm + (size_t)row*DD))[lane] = o4;
}

// ---------------- final: xflat transpose (b,t,d)->(b,d,t) ----------------
__global__ void k_transpose(float* __restrict__ out) {
    __shared__ float tile[32][33];
    int b = blockIdx.x, t0 = blockIdx.y << 5, d0 = blockIdx.z << 5;
    int tx = threadIdx.x, ty = threadIdx.y;  // 32x8
    const float* src = g_xm + (size_t)b*DD*TT;
    #pragma unroll
    for (int r = ty; r < 32; r += 8)
        tile[r][tx] = src[(size_t)(t0+r)*DD + d0 + tx];
    __syncthreads();
    float* dst = out + (size_t)b*DD*TT;
    #pragma unroll
    for (int r = ty; r < 32; r += 8)
        dst[(size_t)(d0+r)*TT + t0 + tx] = tile[tx][r];
}

// ---------------- final: pred = xflat @ fc_w^T + fc_b ----------------
__global__ void k_pred(const float* __restrict__ xflat, const float* __restrict__ fcw,
                       const float* __restrict__ fcb, float* __restrict__ pred) {
    int b = blockIdx.x, tid = threadIdx.x;
    float acc[18];
    #pragma unroll
    for (int c = 0; c < 18; c++) acc[c] = 0.f;
    const float* xr = xflat + (size_t)b*32768;
    for (int k = tid; k < 32768; k += 256) {
        float x = xr[k];
        #pragma unroll
        for (int c = 0; c < 18; c++)
            acc[c] = fmaf(x, fcw[(size_t)c*32768 + k], acc[c]);
    }
    __shared__ float red[8*18];
    int lane = tid & 31, wid = tid >> 5;
    #pragma unroll
    for (int c = 0; c < 18; c++) {
        float s = acc[c];
        #pragma unroll
        for (int o = 16; o > 0; o >>= 1) s += __shfl_xor_sync(0xffffffffu, s, o);
        if (lane == 0) red[wid*18 + c] = s;
    }
    __syncthreads();
    if (tid < 18) {
        float s = fcb[tid];
        #pragma unroll
        for (int w = 0; w < 8; w++) s += red[w*18 + tid];
        pred[b*18 + tid] = s;
    }
}

// ---------------- launch ----------------
extern "C" void kernel_launch(void* const* d_in, const int* in_sizes, int n_in,
                              void* d_out, int out_size) {
    const float* inp   = (const float*)d_in[0];
    const float* emb_w = (const float*)d_in[1];
    const float* emb_b = (const float*)d_in[2];
    const float* dww   = (const float*)d_in[3];
    const float* dwb   = (const float*)d_in[4];
    const float* pww   = (const float*)d_in[5];
    const float* pwb   = (const float*)d_in[6];
    const float* sw1   = (const float*)d_in[7];
    const float* sb1   = (const float*)d_in[8];
    const float* sw2   = (const float*)d_in[9];
    const float* sb2   = (const float*)d_in[10];
    const float* minw  = (const float*)d_in[11];
    const float* mcw   = (const float*)d_in[12];
    const float* mcb   = (const float*)d_in[13];
    const float* mxp   = (const float*)d_in[14];
    const float* mdtw  = (const float*)d_in[15];
    const float* mdtb  = (const float*)d_in[16];
    const float* mAlog = (const float*)d_in[17];
    const float* mD    = (const float*)d_in[18];
    const float* mow   = (const float*)d_in[19];
    const float* lng   = (const float*)d_in[20];
    const float* lnb   = (const float*)d_in[21];
    const float* fcw   = (const float*)d_in[22];
    const float* fcb   = (const float*)d_in[23];
    float* out = (float*)d_out;

    float *pxm, *pxz, *pxc, *pdbl, *py, *pmo;
    cudaGetSymbolAddress((void**)&pxm,  g_xm);
    cudaGetSymbolAddress((void**)&pxz,  g_xz);
    cudaGetSymbolAddress((void**)&pxc,  g_xc);
    cudaGetSymbolAddress((void**)&pdbl, g_dbl);
    cudaGetSymbolAddress((void**)&py,   g_y);
    cudaGetSymbolAddress((void**)&pmo,  g_mo);

    // embedding
    k_embed<<<NBM, 256>>>(inp, emb_w, emb_b);

    // 3 conv blocks
    for (int li = 0; li < 3; li++) {
        k_dwconv<<<NBM*DD, 256>>>(dww, dwb, li);
        k_se<<<NBM, 128>>>(pww, pwb, sw1, sb1, sw2, sb2, li);
        dim3 gpw(4, NBM);
        k_pw_mma<<<gpw, 256>>>(pww, pwb, li);
    }

    // pool -> (b,t,d)
    k_pool<<<BATCH*DD, 256>>>();

    // 2 mamba layers
    for (int li = 0; li < 2; li++) {
        dim3 gxz(16384/128, 512/64);
        k_gemm_mma<<<gxz, 256>>>(pxm, minw + (size_t)li*512*DD, pxz, 16384, 512, 128);
        k_conv_silu<<<(BATCH*TT*DI_)/256, 256>>>(mcw, mcb, li);
        dim3 gdb(16384/128, 1);
        k_gemm_mma<<<gdb, 256>>>(pxc, mxp + (size_t)li*40*DI_, pdbl, 16384, 40, 256);
        k_dtsplit<<<BATCH*TT, 256>>>(mdtw, mdtb, li);
        k_scan<<<BATCH, 256>>>(mAlog, mD, li);
        dim3 gout(16384/128, 2);
        k_gemm_mma<<<gout, 256>>>(py, mow + (size_t)li*DD*DI_, pmo, 16384, 128, 256);
        k_ln<<<16384/8, 256>>>(lng, lnb, li);
    }

    // outputs: xflat (64*32768) then pred (64*18)
    dim3 gt(BATCH, TT/32, DD/32);
    k_transpose<<<gt, dim3(32, 8)>>>(out);
    k_pred<<<BATCH, 256>>>(out, fcw, fcb, out + (size_t)BATCH*DD*TT);
}